// round 6
// baseline (speedup 1.0000x reference)
#include <cuda_runtime.h>
#include <cuda_bf16.h>
#include <cstdint>

#define NB 2
#define NN 384
#define TFv 22
#define POSv 32
#define TPROJv 33
#define CSv 256
#define CZv 128
#define LN_EPS 1e-5f
#define PI_F 3.14159265358979323846f

// rel in [-999, 999] -> index rel+1000; table sized 2048 for safety.
__device__ float g_table[2048 * CZv];
__device__ float g_eL[NB * NN * CZv];
__device__ float g_eR[NB * NN * CZv];
// Pre-split edge weights (hi/lo bf16), [c][k] row-major, 128x128 each.
__device__ __nv_bfloat16 g_W1h[CZv * CZv], g_W1l[CZv * CZv];
__device__ __nv_bfloat16 g_W2h[CZv * CZv], g_W2l[CZv * CZv];

// ---------------------------------------------------------------------------
// helpers
// ---------------------------------------------------------------------------
__device__ __forceinline__ uint32_t smem_u32(const void* p) {
    uint32_t a;
    asm("{ .reg .u64 t; cvta.to.shared.u64 t, %1; cvt.u32.u64 %0, t; }"
        : "=r"(a) : "l"(p));
    return a;
}
__device__ __forceinline__ uint32_t pack_hi2(float x0, float x1, float& r0, float& r1) {
    __nv_bfloat162 v = __floats2bfloat162_rn(x0, x1);
    r0 = x0 - __bfloat162float(__low2bfloat16(v));
    r1 = x1 - __bfloat162float(__high2bfloat16(v));
    return *reinterpret_cast<uint32_t*>(&v);
}
__device__ __forceinline__ uint32_t pack_lo2(float r0, float r1) {
    __nv_bfloat162 v = __floats2bfloat162_rn(r0, r1);
    return *reinterpret_cast<uint32_t*>(&v);
}
__device__ __forceinline__ void mma16816(float* c, uint32_t a0, uint32_t a1,
                                         uint32_t a2, uint32_t a3,
                                         uint32_t b0, uint32_t b1) {
    asm volatile(
        "mma.sync.aligned.m16n8k16.row.col.f32.bf16.bf16.f32 "
        "{%0,%1,%2,%3}, {%4,%5,%6,%7}, {%8,%9}, {%0,%1,%2,%3};"
        : "+f"(c[0]), "+f"(c[1]), "+f"(c[2]), "+f"(c[3])
        : "r"(a0), "r"(a1), "r"(a2), "r"(a3), "r"(b0), "r"(b1));
}
__device__ __forceinline__ void ldsm_x4(uint32_t& r0, uint32_t& r1,
                                        uint32_t& r2, uint32_t& r3, uint32_t addr) {
    asm volatile("ldmatrix.sync.aligned.m8n8.x4.shared.b16 {%0,%1,%2,%3}, [%4];"
                 : "=r"(r0), "=r"(r1), "=r"(r2), "=r"(r3) : "r"(addr));
}

// ---------------------------------------------------------------------------
// Kernel 0: split edge weights into bf16 hi/lo.
// ---------------------------------------------------------------------------
__global__ void prep_w(const float* __restrict__ W1, const float* __restrict__ W2) {
    int t = blockIdx.x * 256 + threadIdx.x;
    if (t < CZv * CZv) {
        float w1 = W1[t], w2 = W2[t];
        __nv_bfloat16 h1 = __float2bfloat16(w1);
        __nv_bfloat16 h2 = __float2bfloat16(w2);
        g_W1h[t] = h1;
        g_W1l[t] = __float2bfloat16(w1 - __bfloat162float(h1));
        g_W2h[t] = h2;
        g_W2l[t] = __float2bfloat16(w2 - __bfloat162float(h2));
    }
}

// ---------------------------------------------------------------------------
// Kernel 1: relative-position table (W_epos cached in padded smem).
// ---------------------------------------------------------------------------
__global__ void table_kernel(const float* __restrict__ W_epos,
                             const float* __restrict__ b_epos,
                             const float* __restrict__ b_etf,
                             const float* __restrict__ b_etime) {
    __shared__ float sWe[CZv * 33];
    __shared__ float emb[POSv];
    const int t = threadIdx.x;  // 0..127
    for (int m = t; m < CZv * POSv; m += 128)
        sWe[(m >> 5) * 33 + (m & 31)] = W_epos[m];
    const int relv = (int)blockIdx.x - 1000;
    if (t < 16) {
        float p = powf(2056.0f, (float)t * (1.0f / 16.0f));
        float ang = ((float)relv * PI_F) / p;
        emb[t] = sinf(ang);
        emb[t + 16] = cosf(ang);
    }
    __syncthreads();
    float acc = b_epos[t] + b_etf[t] + b_etime[t];
#pragma unroll
    for (int k = 0; k < POSv; k++) acc += emb[k] * sWe[t * 33 + k];
    g_table[blockIdx.x * CZv + t] = acc;
}

// ---------------------------------------------------------------------------
// Kernel 2: node path + per-node edge L/R precompute (unchanged, correct).
// ---------------------------------------------------------------------------
#define NR 8
__global__ __launch_bounds__(256) void node_kernel(
    const int* __restrict__ seq_idx, const float* __restrict__ seq_feat,
    const float* __restrict__ timestep, const float* __restrict__ frame_mask,
    const float* __restrict__ W_npos, const float* __restrict__ b_npos,
    const float* __restrict__ W_ntf, const float* __restrict__ b_ntf,
    const float* __restrict__ W_ntime, const float* __restrict__ b_ntime,
    const float* __restrict__ W_n1, const float* __restrict__ b_n1,
    const float* __restrict__ W_n2, const float* __restrict__ b_n2,
    const float* __restrict__ g_n, const float* __restrict__ be_n,
    const float* __restrict__ W_etf, const float* __restrict__ W_etime,
    float* __restrict__ out_seq) {
    __shared__ float spemb[NR][POSv];
    __shared__ float stemb[NR][36];
    __shared__ float sfeat[NR][24];
    __shared__ float sx[NR][CSv];

    const int tid = threadIdx.x;
    const int row0 = blockIdx.x * NR;

    {
        const int r = tid >> 5, j = tid & 31;
        const int row = row0 + r;
        const int b = row / NN;
        if (j < TFv) sfeat[r][j] = seq_feat[row * TFv + j];
        if (j < 16) {
            float p = powf(2056.0f, (float)j * (1.0f / 16.0f));
            float ang = ((float)seq_idx[row] * PI_F) / p;
            spemb[r][j] = sinf(ang);
            spemb[r][j + 16] = cosf(ang);
            float fm = frame_mask[row];
            float tt = timestep[b] * fm;
            float fr = expf(-0.6140226914650789f * (float)j);
            float a2 = tt * fr;
            stemb[r][j] = sinf(a2);
            stemb[r][j + 16] = cosf(a2);
            if (j == 0) stemb[r][32] = fm;
        }
    }
    __syncthreads();

    const int c = tid;
    float acc[NR];
    {
        float base = b_npos[c] + b_ntf[c] + b_ntime[c];
#pragma unroll
        for (int r = 0; r < NR; r++) acc[r] = base;
    }
#pragma unroll
    for (int k = 0; k < POSv; k++) {
        float wv = W_npos[c * POSv + k];
#pragma unroll
        for (int r = 0; r < NR; r++) acc[r] += spemb[r][k] * wv;
    }
#pragma unroll
    for (int k = 0; k < TFv; k++) {
        float wv = W_ntf[c * TFv + k];
#pragma unroll
        for (int r = 0; r < NR; r++) acc[r] += sfeat[r][k] * wv;
    }
#pragma unroll
    for (int k = 0; k < TPROJv; k++) {
        float wv = W_ntime[c * TPROJv + k];
#pragma unroll
        for (int r = 0; r < NR; r++) acc[r] += stemb[r][k] * wv;
    }
#pragma unroll
    for (int r = 0; r < NR; r++) sx[r][c] = fmaxf(acc[r], 0.0f);

    {
        const int c2 = tid & 127, half = tid >> 7;
        float e[NR];
#pragma unroll
        for (int r = 0; r < NR; r++) e[r] = 0.0f;
#pragma unroll
        for (int k = 0; k < TFv; k++) {
            float wv = W_etf[c2 * (2 * TFv) + half * TFv + k];
#pragma unroll
            for (int r = 0; r < NR; r++) e[r] += sfeat[r][k] * wv;
        }
#pragma unroll
        for (int k = 0; k < TPROJv; k++) {
            float wv = W_etime[c2 * (2 * TPROJv) + half * TPROJv + k];
#pragma unroll
            for (int r = 0; r < NR; r++) e[r] += stemb[r][k] * wv;
        }
        float* dst = half ? g_eR : g_eL;
#pragma unroll
        for (int r = 0; r < NR; r++) dst[(row0 + r) * CZv + c2] = e[r];
    }
    __syncthreads();

    float h[NR];
#pragma unroll
    for (int r = 0; r < NR; r++) h[r] = b_n1[c];
    {
        const float4* W1r = (const float4*)(W_n1 + c * CSv);
#pragma unroll 4
        for (int q = 0; q < CSv / 4; q++) {
            float4 wv = W1r[q];
#pragma unroll
            for (int r = 0; r < NR; r++) {
                const float* xr = &sx[r][q * 4];
                h[r] += xr[0] * wv.x + xr[1] * wv.y + xr[2] * wv.z + xr[3] * wv.w;
            }
        }
    }
    __syncthreads();
#pragma unroll
    for (int r = 0; r < NR; r++) sx[r][c] = fmaxf(h[r], 0.0f);
    __syncthreads();

    float o[NR];
#pragma unroll
    for (int r = 0; r < NR; r++) o[r] = b_n2[c];
    {
        const float4* W2r = (const float4*)(W_n2 + c * CSv);
#pragma unroll 4
        for (int q = 0; q < CSv / 4; q++) {
            float4 wv = W2r[q];
#pragma unroll
            for (int r = 0; r < NR; r++) {
                const float* xr = &sx[r][q * 4];
                o[r] += xr[0] * wv.x + xr[1] * wv.y + xr[2] * wv.z + xr[3] * wv.w;
            }
        }
    }
    __syncthreads();
#pragma unroll
    for (int r = 0; r < NR; r++) sx[r][c] = o[r];
    __syncthreads();

    {
        const int w = tid >> 5, l = tid & 31;
        float v[8];
#pragma unroll
        for (int g = 0; g < 8; g++) v[g] = sx[w][g * 32 + l];
        float s = 0.0f;
#pragma unroll
        for (int g = 0; g < 8; g++) s += v[g];
#pragma unroll
        for (int off = 16; off > 0; off >>= 1) s += __shfl_xor_sync(0xffffffffu, s, off);
        float mean = s * (1.0f / 256.0f);
        float sq = 0.0f;
#pragma unroll
        for (int g = 0; g < 8; g++) { float d = v[g] - mean; sq += d * d; }
#pragma unroll
        for (int off = 16; off > 0; off >>= 1) sq += __shfl_xor_sync(0xffffffffu, sq, off);
        float rstd = rsqrtf(sq * (1.0f / 256.0f) + LN_EPS);
        const int row = row0 + w;
#pragma unroll
        for (int g = 0; g < 8; g++) {
            int cc = g * 32 + l;
            out_seq[row * CSv + cc] = (v[g] - mean) * rstd * g_n[cc] + be_n[cc];
        }
    }
}

// ---------------------------------------------------------------------------
// Kernel 3: edge path, bf16x3 emulated-fp32 GEMMs on tensor cores.
// 64-row x 128-col tiles; A (X/H) in smem via ldmatrix; B (W) fragments read
// DIRECTLY from global hi/lo arrays (L1-resident, no smem staging).
// ---------------------------------------------------------------------------
#define WSTR 68           // u32 words per X row (conflict-free)
#define XROWS 64
#define XH_W 0
#define XL_W (XROWS * WSTR)
#define REL_W (2 * XROWS * WSTR)
#define EDGE_SMEM_U32 (REL_W + XROWS + 8)
#define ESTR 132          // epilogue float stride (64x132 overlays X region)

// One bf16x3 GEMM pass for a 32x32 warp tile; B frags via global LDG.
// bgh/bgl: per-lane base = W32 + (n0 + (l>>2))*64 + (l&3)
__device__ __forceinline__ void gemm_pass(
    float acc[2][4][4],
    uint32_t aAddrH, uint32_t aAddrL,
    const uint32_t* __restrict__ bgh, const uint32_t* __restrict__ bgl) {
#pragma unroll
    for (int kk = 0; kk < 8; kk++) {
        const uint32_t kb = kk * 32;
        uint32_t ah[2][4], al[2][4], bh[4][2], bl[4][2];
#pragma unroll
        for (int nt = 0; nt < 4; nt++) {
            const int o = nt * 512 + kk * 8;     // 8 rows * 64 u32/row per nt
            bh[nt][0] = __ldg(bgh + o);
            bh[nt][1] = __ldg(bgh + o + 4);
            bl[nt][0] = __ldg(bgl + o);
            bl[nt][1] = __ldg(bgl + o + 4);
        }
#pragma unroll
        for (int mt = 0; mt < 2; mt++) {
            ldsm_x4(ah[mt][0], ah[mt][1], ah[mt][2], ah[mt][3],
                    aAddrH + mt * (16 * WSTR * 4) + kb);
            ldsm_x4(al[mt][0], al[mt][1], al[mt][2], al[mt][3],
                    aAddrL + mt * (16 * WSTR * 4) + kb);
        }
#pragma unroll
        for (int mt = 0; mt < 2; mt++)
#pragma unroll
            for (int nt = 0; nt < 4; nt++) {
                mma16816(acc[mt][nt], ah[mt][0], ah[mt][1], ah[mt][2], ah[mt][3],
                         bl[nt][0], bl[nt][1]);
                mma16816(acc[mt][nt], al[mt][0], al[mt][1], al[mt][2], al[mt][3],
                         bh[nt][0], bh[nt][1]);
                mma16816(acc[mt][nt], ah[mt][0], ah[mt][1], ah[mt][2], ah[mt][3],
                         bh[nt][0], bh[nt][1]);
            }
    }
}

__global__ __launch_bounds__(256, 3) void edge_kernel(
    const int* __restrict__ seq_idx,
    const float* __restrict__ b_e1, const float* __restrict__ b_e2,
    const float* __restrict__ g_e, const float* __restrict__ be_e,
    float* __restrict__ out_edge) {
    __shared__ uint32_t smw[EDGE_SMEM_U32];
    uint32_t* Xh = smw + XH_W;
    uint32_t* Xl = smw + XL_W;
    int* s_rel = (int*)(smw + REL_W);
    float* E = (float*)smw;  // epilogue overlay

    const int tid = threadIdx.x, w = tid >> 5, l = tid & 31;
    const int g = l >> 2, tig = l & 3;
    const int wm = w >> 2, wn = w & 3;     // 2 x 4 warp grid, 32x32 tiles
    const int m0 = wm * 32, n0 = wn * 32;
    const int bid = blockIdx.x;
    const int jt = bid % 6, i = (bid / 6) % NN, b = bid / (6 * NN);
    const int j0 = jt * XROWS;

    // ldmatrix lane addresses (byte, shared space).
    const uint32_t sb = smem_u32(smw);
    const int rowA = m0 + (l & 15);
    const int kofA = (l >> 4) << 2;
    const uint32_t aAddrH = sb + (rowA * WSTR + kofA) * 4;
    const uint32_t aAddrL = sb + (XL_W + rowA * WSTR + kofA) * 4;

    // B fragment per-lane global bases (u32 index into [n][k/2] array).
    const int bofs = (n0 + g) * 64 + tig;
    const uint32_t* b1h = (const uint32_t*)g_W1h + bofs;
    const uint32_t* b1l = (const uint32_t*)g_W1l + bofs;
    const uint32_t* b2h = (const uint32_t*)g_W2h + bofs;
    const uint32_t* b2l = (const uint32_t*)g_W2l + bofs;

    if (tid < XROWS) {
        int rel = seq_idx[b * NN + i] - seq_idx[b * NN + j0 + tid] + 1000;
        s_rel[tid] = min(max(rel, 0), 2047);
    }
    __syncthreads();

    // Build X = relu(table[rel_j] + L_i + R_j), split to bf16 hi/lo.
    {
        const int r = tid >> 2, seg = tid & 3;  // 4 threads per row, 64 rows
        const float4* tab = (const float4*)(g_table + (size_t)s_rel[r] * CZv) + seg * 8;
        const float4* Rp = (const float4*)(g_eR + (size_t)(b * NN + j0 + r) * CZv) + seg * 8;
        const float4* Lp = (const float4*)(g_eL + (size_t)(b * NN + i) * CZv) + seg * 8;
        unsigned long long* Xh64 = (unsigned long long*)Xh;
        unsigned long long* Xl64 = (unsigned long long*)Xl;
#pragma unroll 4
        for (int q = 0; q < 8; q++) {
            float4 tv = tab[q], rv = Rp[q], lv = Lp[q];
            float x0 = fmaxf(tv.x + lv.x + rv.x, 0.0f);
            float x1 = fmaxf(tv.y + lv.y + rv.y, 0.0f);
            float x2 = fmaxf(tv.z + lv.z + rv.z, 0.0f);
            float x3 = fmaxf(tv.w + lv.w + rv.w, 0.0f);
            float r0, r1, r2, r3;
            uint32_t h01 = pack_hi2(x0, x1, r0, r1);
            uint32_t h23 = pack_hi2(x2, x3, r2, r3);
            int idx64 = r * 34 + seg * 8 + q;
            Xh64[idx64] = ((unsigned long long)h23 << 32) | h01;
            Xl64[idx64] = ((unsigned long long)pack_lo2(r2, r3) << 32) | pack_lo2(r0, r1);
        }
    }
    __syncthreads();

    // ---- GEMM1: acc = X @ W1^T (bf16x3, B from global) ----
    float acc[2][4][4];
#pragma unroll
    for (int mt = 0; mt < 2; mt++)
#pragma unroll
        for (int nt = 0; nt < 4; nt++)
#pragma unroll
            for (int e = 0; e < 4; e++) acc[mt][nt][e] = 0.0f;
    gemm_pass(acc, aAddrH, aAddrL, b1h, b1l);
    __syncthreads();  // all GEMM1 reads of X done

    // H = relu(acc + b_e1) -> X buffers (bf16 hi/lo).
#pragma unroll
    for (int mt = 0; mt < 2; mt++) {
        int r0w = m0 + mt * 16 + g;
#pragma unroll
        for (int nt = 0; nt < 4; nt++) {
            int c0 = n0 + nt * 8 + 2 * tig;
            float bb0 = b_e1[c0], bb1 = b_e1[c0 + 1];
            int cw = c0 >> 1;
            float h0 = fmaxf(acc[mt][nt][0] + bb0, 0.0f);
            float h1 = fmaxf(acc[mt][nt][1] + bb1, 0.0f);
            float h2 = fmaxf(acc[mt][nt][2] + bb0, 0.0f);
            float h3 = fmaxf(acc[mt][nt][3] + bb1, 0.0f);
            float q0, q1, q2, q3;
            Xh[r0w * WSTR + cw] = pack_hi2(h0, h1, q0, q1);
            Xh[(r0w + 8) * WSTR + cw] = pack_hi2(h2, h3, q2, q3);
            Xl[r0w * WSTR + cw] = pack_lo2(q0, q1);
            Xl[(r0w + 8) * WSTR + cw] = pack_lo2(q2, q3);
        }
    }
    __syncthreads();

    // ---- GEMM2: acc = H @ W2^T (bf16x3, B from global) ----
#pragma unroll
    for (int mt = 0; mt < 2; mt++)
#pragma unroll
        for (int nt = 0; nt < 4; nt++)
#pragma unroll
            for (int e = 0; e < 4; e++) acc[mt][nt][e] = 0.0f;
    gemm_pass(acc, aAddrH, aAddrL, b2h, b2l);
    __syncthreads();  // GEMM2 reads done; E overlay now safe

    // O = acc + b_e2 -> E[r][c] (float2 stores, pad 132)
#pragma unroll
    for (int mt = 0; mt < 2; mt++) {
        int r0w = m0 + mt * 16 + g;
#pragma unroll
        for (int nt = 0; nt < 4; nt++) {
            int c0 = n0 + nt * 8 + 2 * tig;
            float bb0 = b_e2[c0], bb1 = b_e2[c0 + 1];
            *(float2*)&E[r0w * ESTR + c0] =
                make_float2(acc[mt][nt][0] + bb0, acc[mt][nt][1] + bb1);
            *(float2*)&E[(r0w + 8) * ESTR + c0] =
                make_float2(acc[mt][nt][2] + bb0, acc[mt][nt][3] + bb1);
        }
    }
    __syncthreads();

    // LayerNorm + coalesced store: warp w handles rows w*8..w*8+7.
    {
        const float ge0 = g_e[l], ge1 = g_e[32 + l], ge2 = g_e[64 + l], ge3 = g_e[96 + l];
        const float be0 = be_e[l], be1 = be_e[32 + l], be2 = be_e[64 + l], be3 = be_e[96 + l];
#pragma unroll 2
        for (int rr = 0; rr < 8; rr++) {
            const int r = w * 8 + rr;
            float v0 = E[r * ESTR + l];
            float v1 = E[r * ESTR + 32 + l];
            float v2 = E[r * ESTR + 64 + l];
            float v3 = E[r * ESTR + 96 + l];
            float s = v0 + v1 + v2 + v3;
#pragma unroll
            for (int off = 16; off > 0; off >>= 1) s += __shfl_xor_sync(0xffffffffu, s, off);
            float mean = s * (1.0f / 128.0f);
            float d0 = v0 - mean, d1 = v1 - mean, d2 = v2 - mean, d3 = v3 - mean;
            float sq = d0 * d0 + d1 * d1 + d2 * d2 + d3 * d3;
#pragma unroll
            for (int off = 16; off > 0; off >>= 1) sq += __shfl_xor_sync(0xffffffffu, sq, off);
            float rstd = rsqrtf(sq * (1.0f / 128.0f) + LN_EPS);
            float* dst = out_edge + ((size_t)(b * NN + i) * NN + (j0 + r)) * CZv;
            dst[l] = d0 * rstd * ge0 + be0;
            dst[32 + l] = d1 * rstd * ge1 + be1;
            dst[64 + l] = d2 * rstd * ge2 + be2;
            dst[96 + l] = d3 * rstd * ge3 + be3;
        }
    }
}

// ===========================================================================
extern "C" void kernel_launch(void* const* d_in, const int* in_sizes, int n_in,
                              void* d_out, int out_size) {
    const int* seq_idx = (const int*)d_in[0];
    const float* seq_feat = (const float*)d_in[1];
    const float* timestep = (const float*)d_in[2];
    const float* frame_mask = (const float*)d_in[3];
    const float* W_npos = (const float*)d_in[4];
    const float* b_npos = (const float*)d_in[5];
    const float* W_ntf = (const float*)d_in[6];
    const float* b_ntf = (const float*)d_in[7];
    const float* W_ntime = (const float*)d_in[8];
    const float* b_ntime = (const float*)d_in[9];
    const float* W_n1 = (const float*)d_in[10];
    const float* b_n1 = (const float*)d_in[11];
    const float* W_n2 = (const float*)d_in[12];
    const float* b_n2 = (const float*)d_in[13];
    const float* g_n = (const float*)d_in[14];
    const float* be_n = (const float*)d_in[15];
    const float* W_epos = (const float*)d_in[16];
    const float* b_epos = (const float*)d_in[17];
    const float* W_etf = (const float*)d_in[18];
    const float* b_etf = (const float*)d_in[19];
    const float* W_etime = (const float*)d_in[20];
    const float* b_etime = (const float*)d_in[21];
    const float* W_e1 = (const float*)d_in[22];
    const float* b_e1 = (const float*)d_in[23];
    const float* W_e2 = (const float*)d_in[24];
    const float* b_e2 = (const float*)d_in[25];
    const float* g_e = (const float*)d_in[26];
    const float* be_e = (const float*)d_in[27];

    float* out = (float*)d_out;
    float* out_seq = out;                   // [B,N,CS] first
    float* out_edge = out + NB * NN * CSv;  // then [B,N,N,CZ]

    prep_w<<<64, 256>>>(W_e1, W_e2);
    table_kernel<<<2048, 128>>>(W_epos, b_epos, b_etf, b_etime);
    node_kernel<<<NB * NN / NR, 256>>>(seq_idx, seq_feat, timestep, frame_mask,
                                       W_npos, b_npos, W_ntf, b_ntf, W_ntime, b_ntime,
                                       W_n1, b_n1, W_n2, b_n2, g_n, be_n,
                                       W_etf, W_etime, out_seq);
    edge_kernel<<<NB * NN * 6, 256>>>(seq_idx, b_e1, b_e2, g_e, be_e, out_edge);
}

// round 7
// speedup vs baseline: 1.8084x; 1.8084x over previous
#include <cuda_runtime.h>
#include <cuda_fp16.h>
#include <cstdint>

#define NB 2
#define NN 384
#define TFv 22
#define POSv 32
#define TPROJv 33
#define CSv 256
#define CZv 128
#define LN_EPS 1e-5f
#define PI_F 3.14159265358979323846f

// rel in [-999, 999] -> index rel+1000; table sized 2048 for safety.
__device__ float g_table[2048 * CZv];
__device__ float g_eL[NB * NN * CZv];
__device__ float g_eR[NB * NN * CZv];
// Edge weights rounded to fp16, [c][k] row-major, 128x128 each.
__device__ __half g_W1f[CZv * CZv], g_W2f[CZv * CZv];

// ---------------------------------------------------------------------------
// helpers
// ---------------------------------------------------------------------------
__device__ __forceinline__ uint32_t smem_u32(const void* p) {
    uint32_t a;
    asm("{ .reg .u64 t; cvta.to.shared.u64 t, %1; cvt.u32.u64 %0, t; }"
        : "=r"(a) : "l"(p));
    return a;
}
// fp16 hi/lo split: returns packed hi pair, residuals out.
__device__ __forceinline__ uint32_t packh_hi2(float x0, float x1, float& r0, float& r1) {
    __half2 v = __floats2half2_rn(x0, x1);
    r0 = x0 - __half2float(__low2half(v));
    r1 = x1 - __half2float(__high2half(v));
    return *reinterpret_cast<uint32_t*>(&v);
}
__device__ __forceinline__ uint32_t packh2(float r0, float r1) {
    __half2 v = __floats2half2_rn(r0, r1);
    return *reinterpret_cast<uint32_t*>(&v);
}
__device__ __forceinline__ void mma16816(float* c, uint32_t a0, uint32_t a1,
                                         uint32_t a2, uint32_t a3,
                                         uint32_t b0, uint32_t b1) {
    asm volatile(
        "mma.sync.aligned.m16n8k16.row.col.f32.f16.f16.f32 "
        "{%0,%1,%2,%3}, {%4,%5,%6,%7}, {%8,%9}, {%0,%1,%2,%3};"
        : "+f"(c[0]), "+f"(c[1]), "+f"(c[2]), "+f"(c[3])
        : "r"(a0), "r"(a1), "r"(a2), "r"(a3), "r"(b0), "r"(b1));
}
__device__ __forceinline__ void ldsm_x4(uint32_t& r0, uint32_t& r1,
                                        uint32_t& r2, uint32_t& r3, uint32_t addr) {
    asm volatile("ldmatrix.sync.aligned.m8n8.x4.shared.b16 {%0,%1,%2,%3}, [%4];"
                 : "=r"(r0), "=r"(r1), "=r"(r2), "=r"(r3) : "r"(addr));
}

// ---------------------------------------------------------------------------
// Kernel 0: round edge weights to fp16.
// ---------------------------------------------------------------------------
__global__ void prep_w(const float* __restrict__ W1, const float* __restrict__ W2) {
    int t = blockIdx.x * 256 + threadIdx.x;
    if (t < CZv * CZv) {
        g_W1f[t] = __float2half_rn(W1[t]);
        g_W2f[t] = __float2half_rn(W2[t]);
    }
}

// ---------------------------------------------------------------------------
// Kernel 1: relative-position table (W_epos cached in padded smem).
// ---------------------------------------------------------------------------
__global__ void table_kernel(const float* __restrict__ W_epos,
                             const float* __restrict__ b_epos,
                             const float* __restrict__ b_etf,
                             const float* __restrict__ b_etime) {
    __shared__ float sWe[CZv * 33];
    __shared__ float emb[POSv];
    const int t = threadIdx.x;  // 0..127
    for (int m = t; m < CZv * POSv; m += 128)
        sWe[(m >> 5) * 33 + (m & 31)] = W_epos[m];
    const int relv = (int)blockIdx.x - 1000;
    if (t < 16) {
        float p = powf(2056.0f, (float)t * (1.0f / 16.0f));
        float ang = ((float)relv * PI_F) / p;
        emb[t] = sinf(ang);
        emb[t + 16] = cosf(ang);
    }
    __syncthreads();
    float acc = b_epos[t] + b_etf[t] + b_etime[t];
#pragma unroll
    for (int k = 0; k < POSv; k++) acc += emb[k] * sWe[t * 33 + k];
    g_table[blockIdx.x * CZv + t] = acc;
}

// ---------------------------------------------------------------------------
// Kernel 2: node path + per-node edge L/R precompute (unchanged, correct).
// ---------------------------------------------------------------------------
#define NR 8
__global__ __launch_bounds__(256) void node_kernel(
    const int* __restrict__ seq_idx, const float* __restrict__ seq_feat,
    const float* __restrict__ timestep, const float* __restrict__ frame_mask,
    const float* __restrict__ W_npos, const float* __restrict__ b_npos,
    const float* __restrict__ W_ntf, const float* __restrict__ b_ntf,
    const float* __restrict__ W_ntime, const float* __restrict__ b_ntime,
    const float* __restrict__ W_n1, const float* __restrict__ b_n1,
    const float* __restrict__ W_n2, const float* __restrict__ b_n2,
    const float* __restrict__ g_n, const float* __restrict__ be_n,
    const float* __restrict__ W_etf, const float* __restrict__ W_etime,
    float* __restrict__ out_seq) {
    __shared__ float spemb[NR][POSv];
    __shared__ float stemb[NR][36];
    __shared__ float sfeat[NR][24];
    __shared__ float sx[NR][CSv];

    const int tid = threadIdx.x;
    const int row0 = blockIdx.x * NR;

    {
        const int r = tid >> 5, j = tid & 31;
        const int row = row0 + r;
        const int b = row / NN;
        if (j < TFv) sfeat[r][j] = seq_feat[row * TFv + j];
        if (j < 16) {
            float p = powf(2056.0f, (float)j * (1.0f / 16.0f));
            float ang = ((float)seq_idx[row] * PI_F) / p;
            spemb[r][j] = sinf(ang);
            spemb[r][j + 16] = cosf(ang);
            float fm = frame_mask[row];
            float tt = timestep[b] * fm;
            float fr = expf(-0.6140226914650789f * (float)j);
            float a2 = tt * fr;
            stemb[r][j] = sinf(a2);
            stemb[r][j + 16] = cosf(a2);
            if (j == 0) stemb[r][32] = fm;
        }
    }
    __syncthreads();

    const int c = tid;
    float acc[NR];
    {
        float base = b_npos[c] + b_ntf[c] + b_ntime[c];
#pragma unroll
        for (int r = 0; r < NR; r++) acc[r] = base;
    }
#pragma unroll
    for (int k = 0; k < POSv; k++) {
        float wv = W_npos[c * POSv + k];
#pragma unroll
        for (int r = 0; r < NR; r++) acc[r] += spemb[r][k] * wv;
    }
#pragma unroll
    for (int k = 0; k < TFv; k++) {
        float wv = W_ntf[c * TFv + k];
#pragma unroll
        for (int r = 0; r < NR; r++) acc[r] += sfeat[r][k] * wv;
    }
#pragma unroll
    for (int k = 0; k < TPROJv; k++) {
        float wv = W_ntime[c * TPROJv + k];
#pragma unroll
        for (int r = 0; r < NR; r++) acc[r] += stemb[r][k] * wv;
    }
#pragma unroll
    for (int r = 0; r < NR; r++) sx[r][c] = fmaxf(acc[r], 0.0f);

    {
        const int c2 = tid & 127, half = tid >> 7;
        float e[NR];
#pragma unroll
        for (int r = 0; r < NR; r++) e[r] = 0.0f;
#pragma unroll
        for (int k = 0; k < TFv; k++) {
            float wv = W_etf[c2 * (2 * TFv) + half * TFv + k];
#pragma unroll
            for (int r = 0; r < NR; r++) e[r] += sfeat[r][k] * wv;
        }
#pragma unroll
        for (int k = 0; k < TPROJv; k++) {
            float wv = W_etime[c2 * (2 * TPROJv) + half * TPROJv + k];
#pragma unroll
            for (int r = 0; r < NR; r++) e[r] += stemb[r][k] * wv;
        }
        float* dst = half ? g_eR : g_eL;
#pragma unroll
        for (int r = 0; r < NR; r++) dst[(row0 + r) * CZv + c2] = e[r];
    }
    __syncthreads();

    float h[NR];
#pragma unroll
    for (int r = 0; r < NR; r++) h[r] = b_n1[c];
    {
        const float4* W1r = (const float4*)(W_n1 + c * CSv);
#pragma unroll 4
        for (int q = 0; q < CSv / 4; q++) {
            float4 wv = W1r[q];
#pragma unroll
            for (int r = 0; r < NR; r++) {
                const float* xr = &sx[r][q * 4];
                h[r] += xr[0] * wv.x + xr[1] * wv.y + xr[2] * wv.z + xr[3] * wv.w;
            }
        }
    }
    __syncthreads();
#pragma unroll
    for (int r = 0; r < NR; r++) sx[r][c] = fmaxf(h[r], 0.0f);
    __syncthreads();

    float o[NR];
#pragma unroll
    for (int r = 0; r < NR; r++) o[r] = b_n2[c];
    {
        const float4* W2r = (const float4*)(W_n2 + c * CSv);
#pragma unroll 4
        for (int q = 0; q < CSv / 4; q++) {
            float4 wv = W2r[q];
#pragma unroll
            for (int r = 0; r < NR; r++) {
                const float* xr = &sx[r][q * 4];
                o[r] += xr[0] * wv.x + xr[1] * wv.y + xr[2] * wv.z + xr[3] * wv.w;
            }
        }
    }
    __syncthreads();
#pragma unroll
    for (int r = 0; r < NR; r++) sx[r][c] = o[r];
    __syncthreads();

    {
        const int w = tid >> 5, l = tid & 31;
        float v[8];
#pragma unroll
        for (int g = 0; g < 8; g++) v[g] = sx[w][g * 32 + l];
        float s = 0.0f;
#pragma unroll
        for (int g = 0; g < 8; g++) s += v[g];
#pragma unroll
        for (int off = 16; off > 0; off >>= 1) s += __shfl_xor_sync(0xffffffffu, s, off);
        float mean = s * (1.0f / 256.0f);
        float sq = 0.0f;
#pragma unroll
        for (int g = 0; g < 8; g++) { float d = v[g] - mean; sq += d * d; }
#pragma unroll
        for (int off = 16; off > 0; off >>= 1) sq += __shfl_xor_sync(0xffffffffu, sq, off);
        float rstd = rsqrtf(sq * (1.0f / 256.0f) + LN_EPS);
        const int row = row0 + w;
#pragma unroll
        for (int g = 0; g < 8; g++) {
            int cc = g * 32 + l;
            out_seq[row * CSv + cc] = (v[g] - mean) * rstd * g_n[cc] + be_n[cc];
        }
    }
}

// ---------------------------------------------------------------------------
// Kernel 3: edge path, fp16x2 GEMMs on tensor cores.
// 128x128 tile, 8 warps (2x4 grid of 64x32 warp tiles), W single fp16,
// X/H split fp16 hi/lo.  All operands via smem + ldmatrix (L1-optimal).
// ---------------------------------------------------------------------------
#define WSTR 68           // u32 words per row (conflict-free: 68 mod 32 = 4)
#define XH_W 0
#define XL_W (128 * WSTR)
#define WS_W (2 * 128 * WSTR)
#define REL_W (3 * 128 * WSTR)
#define EDGE_SMEM_U32 (REL_W + 128 + 8)
#define EDGE_SMEM_BYTES (EDGE_SMEM_U32 * 4)
#define ESTR 132          // epilogue float stride (128x132 overlays Xh+Xl)

// fp16x2 GEMM pass, warp tile 64x32: acc[4][4][4].
__device__ __forceinline__ void gemm_pass(
    float acc[4][4][4],
    uint32_t aAddrH, uint32_t aAddrL,   // ldsm lane addr (mt=0, kk=0)
    uint32_t bAddr) {                   // ldsm lane addr (p=0, kk=0)
#pragma unroll
    for (int kk = 0; kk < 8; kk++) {
        const uint32_t kb = kk * 32;
        uint32_t bh[4][2];
#pragma unroll
        for (int p = 0; p < 2; p++)
            ldsm_x4(bh[2 * p][0], bh[2 * p][1], bh[2 * p + 1][0], bh[2 * p + 1][1],
                    bAddr + p * (16 * WSTR * 4) + kb);
#pragma unroll
        for (int mh = 0; mh < 2; mh++) {
            uint32_t ah[2][4], al[2][4];
#pragma unroll
            for (int mt = 0; mt < 2; mt++) {
                ldsm_x4(ah[mt][0], ah[mt][1], ah[mt][2], ah[mt][3],
                        aAddrH + (mh * 2 + mt) * (16 * WSTR * 4) + kb);
                ldsm_x4(al[mt][0], al[mt][1], al[mt][2], al[mt][3],
                        aAddrL + (mh * 2 + mt) * (16 * WSTR * 4) + kb);
            }
#pragma unroll
            for (int mt = 0; mt < 2; mt++)
#pragma unroll
                for (int nt = 0; nt < 4; nt++) {
                    mma16816(acc[mh * 2 + mt][nt],
                             al[mt][0], al[mt][1], al[mt][2], al[mt][3],
                             bh[nt][0], bh[nt][1]);
                    mma16816(acc[mh * 2 + mt][nt],
                             ah[mt][0], ah[mt][1], ah[mt][2], ah[mt][3],
                             bh[nt][0], bh[nt][1]);
                }
        }
    }
}

__global__ __launch_bounds__(256, 2) void edge_kernel(
    const int* __restrict__ seq_idx,
    const float* __restrict__ b_e1, const float* __restrict__ b_e2,
    const float* __restrict__ g_e, const float* __restrict__ be_e,
    float* __restrict__ out_edge) {
    extern __shared__ uint32_t smw[];
    uint32_t* Xh = smw + XH_W;
    uint32_t* Xl = smw + XL_W;
    uint32_t* Ws = smw + WS_W;
    int* s_rel = (int*)(smw + REL_W);
    float* E = (float*)smw;  // epilogue overlay: 128x132 floats < Xh+Xl region

    const int tid = threadIdx.x, w = tid >> 5, l = tid & 31;
    const int g = l >> 2, tig = l & 3;
    const int wm = w >> 2, wn = w & 3;     // 2 x 4 warp grid, 64x32 tiles
    const int m0 = wm * 64, n0 = wn * 32;
    const int bid = blockIdx.x;
    const int jt = bid % 3, i = (bid / 3) % NN, b = bid / (3 * NN);
    const int j0 = jt * 128;

    // ldmatrix lane addresses (byte, shared space).
    const uint32_t sb = smem_u32(smw);
    const int rowA = m0 + (l & 15);
    const int kofA = (l >> 4) << 2;
    const uint32_t aAddrH = sb + (rowA * WSTR + kofA) * 4;
    const uint32_t aAddrL = sb + (XL_W + rowA * WSTR + kofA) * 4;
    const int nB = n0 + (l & 7) + ((l >> 4) << 3);
    const int kofB = ((l >> 3) & 1) << 2;
    const uint32_t bAddr = sb + (WS_W + nB * WSTR + kofB) * 4;

    if (tid < 128) {
        int rel = seq_idx[b * NN + i] - seq_idx[b * NN + j0 + tid] + 1000;
        s_rel[tid] = min(max(rel, 0), 2047);
    }
    // stage W1 (fp16, padded rows): 2048 float4
    {
        const float4* Wsrc = (const float4*)g_W1f;
        for (int m = tid; m < 2048; m += 256) {
            int n = m >> 4, c4 = m & 15;
            *(float4*)&Ws[n * WSTR + c4 * 4] = Wsrc[m];
        }
    }
    __syncthreads();

    // Build X = relu(table[rel_j] + L_i + R_j), split to fp16 hi/lo.
    {
        const int r = tid >> 1, seg = tid & 1;  // 2 threads per row, 128 rows
        const float4* tab = (const float4*)(g_table + (size_t)s_rel[r] * CZv) + seg * 16;
        const float4* Rp = (const float4*)(g_eR + (size_t)(b * NN + j0 + r) * CZv) + seg * 16;
        const float4* Lp = (const float4*)(g_eL + (size_t)(b * NN + i) * CZv) + seg * 16;
        unsigned long long* Xh64 = (unsigned long long*)Xh;
        unsigned long long* Xl64 = (unsigned long long*)Xl;
#pragma unroll 4
        for (int q = 0; q < 16; q++) {
            float4 tv = tab[q], rv = Rp[q], lv = Lp[q];
            float x0 = fmaxf(tv.x + lv.x + rv.x, 0.0f);
            float x1 = fmaxf(tv.y + lv.y + rv.y, 0.0f);
            float x2 = fmaxf(tv.z + lv.z + rv.z, 0.0f);
            float x3 = fmaxf(tv.w + lv.w + rv.w, 0.0f);
            float r0, r1, r2, r3;
            uint32_t h01 = packh_hi2(x0, x1, r0, r1);
            uint32_t h23 = packh_hi2(x2, x3, r2, r3);
            int idx64 = r * 34 + seg * 16 + q;
            Xh64[idx64] = ((unsigned long long)h23 << 32) | h01;
            Xl64[idx64] = ((unsigned long long)packh2(r2, r3) << 32) | packh2(r0, r1);
        }
    }
    __syncthreads();

    // ---- GEMM1: acc = X @ W1^T (fp16x2) ----
    float acc[4][4][4];
#pragma unroll
    for (int mt = 0; mt < 4; mt++)
#pragma unroll
        for (int nt = 0; nt < 4; nt++)
#pragma unroll
            for (int e = 0; e < 4; e++) acc[mt][nt][e] = 0.0f;
    gemm_pass(acc, aAddrH, aAddrL, bAddr);
    __syncthreads();  // all GEMM1 reads of X/W done

    // H = relu(acc + b_e1) -> X buffers (fp16 hi/lo); stage W2.
#pragma unroll
    for (int mt = 0; mt < 4; mt++) {
        int r0w = m0 + mt * 16 + g;
#pragma unroll
        for (int nt = 0; nt < 4; nt++) {
            int c0 = n0 + nt * 8 + 2 * tig;
            float bb0 = b_e1[c0], bb1 = b_e1[c0 + 1];
            int cw = c0 >> 1;
            float h0 = fmaxf(acc[mt][nt][0] + bb0, 0.0f);
            float h1 = fmaxf(acc[mt][nt][1] + bb1, 0.0f);
            float h2 = fmaxf(acc[mt][nt][2] + bb0, 0.0f);
            float h3 = fmaxf(acc[mt][nt][3] + bb1, 0.0f);
            float q0, q1, q2, q3;
            Xh[r0w * WSTR + cw] = packh_hi2(h0, h1, q0, q1);
            Xh[(r0w + 8) * WSTR + cw] = packh_hi2(h2, h3, q2, q3);
            Xl[r0w * WSTR + cw] = packh2(q0, q1);
            Xl[(r0w + 8) * WSTR + cw] = packh2(q2, q3);
        }
    }
    {
        const float4* Wsrc = (const float4*)g_W2f;
        for (int m = tid; m < 2048; m += 256) {
            int n = m >> 4, c4 = m & 15;
            *(float4*)&Ws[n * WSTR + c4 * 4] = Wsrc[m];
        }
    }
    __syncthreads();

    // ---- GEMM2: acc = H @ W2^T (fp16x2) ----
#pragma unroll
    for (int mt = 0; mt < 4; mt++)
#pragma unroll
        for (int nt = 0; nt < 4; nt++)
#pragma unroll
            for (int e = 0; e < 4; e++) acc[mt][nt][e] = 0.0f;
    gemm_pass(acc, aAddrH, aAddrL, bAddr);
    __syncthreads();  // GEMM2 reads done; E overlay now safe

    // O = acc + b_e2 -> E[r][c] (float2 stores, pad 132)
#pragma unroll
    for (int mt = 0; mt < 4; mt++) {
        int r0w = m0 + mt * 16 + g;
#pragma unroll
        for (int nt = 0; nt < 4; nt++) {
            int c0 = n0 + nt * 8 + 2 * tig;
            float bb0 = b_e2[c0], bb1 = b_e2[c0 + 1];
            *(float2*)&E[r0w * ESTR + c0] =
                make_float2(acc[mt][nt][0] + bb0, acc[mt][nt][1] + bb1);
            *(float2*)&E[(r0w + 8) * ESTR + c0] =
                make_float2(acc[mt][nt][2] + bb0, acc[mt][nt][3] + bb1);
        }
    }
    __syncthreads();

    // LayerNorm + coalesced store: warp w handles rows w*16..w*16+15.
    {
        const float ge0 = g_e[l], ge1 = g_e[32 + l], ge2 = g_e[64 + l], ge3 = g_e[96 + l];
        const float be0 = be_e[l], be1 = be_e[32 + l], be2 = be_e[64 + l], be3 = be_e[96 + l];
#pragma unroll 2
        for (int rr = 0; rr < 16; rr++) {
            const int r = w * 16 + rr;
            float v0 = E[r * ESTR + l];
            float v1 = E[r * ESTR + 32 + l];
            float v2 = E[r * ESTR + 64 + l];
            float v3 = E[r * ESTR + 96 + l];
            float s = v0 + v1 + v2 + v3;
#pragma unroll
            for (int off = 16; off > 0; off >>= 1) s += __shfl_xor_sync(0xffffffffu, s, off);
            float mean = s * (1.0f / 128.0f);
            float d0 = v0 - mean, d1 = v1 - mean, d2 = v2 - mean, d3 = v3 - mean;
            float sq = d0 * d0 + d1 * d1 + d2 * d2 + d3 * d3;
#pragma unroll
            for (int off = 16; off > 0; off >>= 1) sq += __shfl_xor_sync(0xffffffffu, sq, off);
            float rstd = rsqrtf(sq * (1.0f / 128.0f) + LN_EPS);
            float* dst = out_edge + ((size_t)(b * NN + i) * NN + (j0 + r)) * CZv;
            dst[l] = d0 * rstd * ge0 + be0;
            dst[32 + l] = d1 * rstd * ge1 + be1;
            dst[64 + l] = d2 * rstd * ge2 + be2;
            dst[96 + l] = d3 * rstd * ge3 + be3;
        }
    }
}

// ===========================================================================
extern "C" void kernel_launch(void* const* d_in, const int* in_sizes, int n_in,
                              void* d_out, int out_size) {
    const int* seq_idx = (const int*)d_in[0];
    const float* seq_feat = (const float*)d_in[1];
    const float* timestep = (const float*)d_in[2];
    const float* frame_mask = (const float*)d_in[3];
    const float* W_npos = (const float*)d_in[4];
    const float* b_npos = (const float*)d_in[5];
    const float* W_ntf = (const float*)d_in[6];
    const float* b_ntf = (const float*)d_in[7];
    const float* W_ntime = (const float*)d_in[8];
    const float* b_ntime = (const float*)d_in[9];
    const float* W_n1 = (const float*)d_in[10];
    const float* b_n1 = (const float*)d_in[11];
    const float* W_n2 = (const float*)d_in[12];
    const float* b_n2 = (const float*)d_in[13];
    const float* g_n = (const float*)d_in[14];
    const float* be_n = (const float*)d_in[15];
    const float* W_epos = (const float*)d_in[16];
    const float* b_epos = (const float*)d_in[17];
    const float* W_etf = (const float*)d_in[18];
    const float* b_etf = (const float*)d_in[19];
    const float* W_etime = (const float*)d_in[20];
    const float* b_etime = (const float*)d_in[21];
    const float* W_e1 = (const float*)d_in[22];
    const float* b_e1 = (const float*)d_in[23];
    const float* W_e2 = (const float*)d_in[24];
    const float* b_e2 = (const float*)d_in[25];
    const float* g_e = (const float*)d_in[26];
    const float* be_e = (const float*)d_in[27];

    float* out = (float*)d_out;
    float* out_seq = out;                   // [B,N,CS] first
    float* out_edge = out + NB * NN * CSv;  // then [B,N,N,CZ]

    static int configured = 0;
    if (!configured) {
        cudaFuncSetAttribute(edge_kernel, cudaFuncAttributeMaxDynamicSharedMemorySize,
                             EDGE_SMEM_BYTES);
        configured = 1;
    }

    prep_w<<<64, 256>>>(W_e1, W_e2);
    table_kernel<<<2048, 128>>>(W_epos, b_epos, b_etf, b_etime);
    node_kernel<<<NB * NN / NR, 256>>>(seq_idx, seq_feat, timestep, frame_mask,
                                       W_npos, b_npos, W_ntf, b_ntf, W_ntime, b_ntime,
                                       W_n1, b_n1, W_n2, b_n2, g_n, be_n,
                                       W_etf, W_etime, out_seq);
    edge_kernel<<<NB * NN * 3, 256, EDGE_SMEM_BYTES>>>(seq_idx, b_e1, b_e2,
                                                       g_e, be_e, out_edge);
}

// round 9
// speedup vs baseline: 2.2203x; 1.2278x over previous
#include <cuda_runtime.h>
#include <cuda_fp16.h>
#include <cstdint>

#define NB 2
#define NN 384
#define TFv 22
#define POSv 32
#define TPROJv 33
#define CSv 256
#define CZv 128
#define LN_EPS 1e-5f
#define PI_F 3.14159265358979323846f

// rel in [-999, 999] -> index rel+1000; table sized 2048 for safety.
__device__ float g_table[2048 * CZv];
__device__ float g_eL[NB * NN * CZv];
__device__ float g_eR[NB * NN * CZv];
// Edge weights rounded to fp16, [c][k] row-major, 128x128 each.
__device__ __half g_W1f[CZv * CZv], g_W2f[CZv * CZv];

// ---------------------------------------------------------------------------
// helpers
// ---------------------------------------------------------------------------
__device__ __forceinline__ uint32_t smem_u32(const void* p) {
    uint32_t a;
    asm("{ .reg .u64 t; cvta.to.shared.u64 t, %1; cvt.u32.u64 %0, t; }"
        : "=r"(a) : "l"(p));
    return a;
}
__device__ __forceinline__ uint32_t packh_hi2(float x0, float x1, float& r0, float& r1) {
    __half2 v = __floats2half2_rn(x0, x1);
    r0 = x0 - __half2float(__low2half(v));
    r1 = x1 - __half2float(__high2half(v));
    return *reinterpret_cast<uint32_t*>(&v);
}
__device__ __forceinline__ uint32_t packh2(float r0, float r1) {
    __half2 v = __floats2half2_rn(r0, r1);
    return *reinterpret_cast<uint32_t*>(&v);
}
__device__ __forceinline__ void mma16816(float* c, uint32_t a0, uint32_t a1,
                                         uint32_t a2, uint32_t a3,
                                         uint32_t b0, uint32_t b1) {
    asm volatile(
        "mma.sync.aligned.m16n8k16.row.col.f32.f16.f16.f32 "
        "{%0,%1,%2,%3}, {%4,%5,%6,%7}, {%8,%9}, {%0,%1,%2,%3};"
        : "+f"(c[0]), "+f"(c[1]), "+f"(c[2]), "+f"(c[3])
        : "r"(a0), "r"(a1), "r"(a2), "r"(a3), "r"(b0), "r"(b1));
}
__device__ __forceinline__ void ldsm_x4(uint32_t& r0, uint32_t& r1,
                                        uint32_t& r2, uint32_t& r3, uint32_t addr) {
    asm volatile("ldmatrix.sync.aligned.m8n8.x4.shared.b16 {%0,%1,%2,%3}, [%4];"
                 : "=r"(r0), "=r"(r1), "=r"(r2), "=r"(r3) : "r"(addr));
}
__device__ __forceinline__ void stsm_x4(uint32_t addr, uint32_t r0, uint32_t r1,
                                        uint32_t r2, uint32_t r3) {
    asm volatile("stmatrix.sync.aligned.m8n8.x4.shared.b16 [%0], {%1,%2,%3,%4};"
                 :: "r"(addr), "r"(r0), "r"(r1), "r"(r2), "r"(r3) : "memory");
}

// ---------------------------------------------------------------------------
// Kernel 0: round edge weights to fp16.
// ---------------------------------------------------------------------------
__global__ void prep_w(const float* __restrict__ W1, const float* __restrict__ W2) {
    int t = blockIdx.x * 256 + threadIdx.x;
    if (t < CZv * CZv) {
        g_W1f[t] = __float2half_rn(W1[t]);
        g_W2f[t] = __float2half_rn(W2[t]);
    }
}

// ---------------------------------------------------------------------------
// Kernel 1: relative-position table (W_epos cached in padded smem).
// ---------------------------------------------------------------------------
__global__ void table_kernel(const float* __restrict__ W_epos,
                             const float* __restrict__ b_epos,
                             const float* __restrict__ b_etf,
                             const float* __restrict__ b_etime) {
    __shared__ float sWe[CZv * 33];
    __shared__ float emb[POSv];
    const int t = threadIdx.x;  // 0..127
    for (int m = t; m < CZv * POSv; m += 128)
        sWe[(m >> 5) * 33 + (m & 31)] = W_epos[m];
    const int relv = (int)blockIdx.x - 1000;
    if (t < 16) {
        float p = powf(2056.0f, (float)t * (1.0f / 16.0f));
        float ang = ((float)relv * PI_F) / p;
        emb[t] = sinf(ang);
        emb[t + 16] = cosf(ang);
    }
    __syncthreads();
    float acc = b_epos[t] + b_etf[t] + b_etime[t];
#pragma unroll
    for (int k = 0; k < POSv; k++) acc += emb[k] * sWe[t * 33 + k];
    g_table[blockIdx.x * CZv + t] = acc;
}

// ---------------------------------------------------------------------------
// Kernel 2: node path + per-node edge L/R precompute (unchanged, correct).
// ---------------------------------------------------------------------------
#define NR 8
__global__ __launch_bounds__(256) void node_kernel(
    const int* __restrict__ seq_idx, const float* __restrict__ seq_feat,
    const float* __restrict__ timestep, const float* __restrict__ frame_mask,
    const float* __restrict__ W_npos, const float* __restrict__ b_npos,
    const float* __restrict__ W_ntf, const float* __restrict__ b_ntf,
    const float* __restrict__ W_ntime, const float* __restrict__ b_ntime,
    const float* __restrict__ W_n1, const float* __restrict__ b_n1,
    const float* __restrict__ W_n2, const float* __restrict__ b_n2,
    const float* __restrict__ g_n, const float* __restrict__ be_n,
    const float* __restrict__ W_etf, const float* __restrict__ W_etime,
    float* __restrict__ out_seq) {
    __shared__ float spemb[NR][POSv];
    __shared__ float stemb[NR][36];
    __shared__ float sfeat[NR][24];
    __shared__ float sx[NR][CSv];

    const int tid = threadIdx.x;
    const int row0 = blockIdx.x * NR;

    {
        const int r = tid >> 5, j = tid & 31;
        const int row = row0 + r;
        const int b = row / NN;
        if (j < TFv) sfeat[r][j] = seq_feat[row * TFv + j];
        if (j < 16) {
            float p = powf(2056.0f, (float)j * (1.0f / 16.0f));
            float ang = ((float)seq_idx[row] * PI_F) / p;
            spemb[r][j] = sinf(ang);
            spemb[r][j + 16] = cosf(ang);
            float fm = frame_mask[row];
            float tt = timestep[b] * fm;
            float fr = expf(-0.6140226914650789f * (float)j);
            float a2 = tt * fr;
            stemb[r][j] = sinf(a2);
            stemb[r][j + 16] = cosf(a2);
            if (j == 0) stemb[r][32] = fm;
        }
    }
    __syncthreads();

    const int c = tid;
    float acc[NR];
    {
        float base = b_npos[c] + b_ntf[c] + b_ntime[c];
#pragma unroll
        for (int r = 0; r < NR; r++) acc[r] = base;
    }
#pragma unroll
    for (int k = 0; k < POSv; k++) {
        float wv = W_npos[c * POSv + k];
#pragma unroll
        for (int r = 0; r < NR; r++) acc[r] += spemb[r][k] * wv;
    }
#pragma unroll
    for (int k = 0; k < TFv; k++) {
        float wv = W_ntf[c * TFv + k];
#pragma unroll
        for (int r = 0; r < NR; r++) acc[r] += sfeat[r][k] * wv;
    }
#pragma unroll
    for (int k = 0; k < TPROJv; k++) {
        float wv = W_ntime[c * TPROJv + k];
#pragma unroll
        for (int r = 0; r < NR; r++) acc[r] += stemb[r][k] * wv;
    }
#pragma unroll
    for (int r = 0; r < NR; r++) sx[r][c] = fmaxf(acc[r], 0.0f);

    {
        const int c2 = tid & 127, half = tid >> 7;
        float e[NR];
#pragma unroll
        for (int r = 0; r < NR; r++) e[r] = 0.0f;
#pragma unroll
        for (int k = 0; k < TFv; k++) {
            float wv = W_etf[c2 * (2 * TFv) + half * TFv + k];
#pragma unroll
            for (int r = 0; r < NR; r++) e[r] += sfeat[r][k] * wv;
        }
#pragma unroll
        for (int k = 0; k < TPROJv; k++) {
            float wv = W_etime[c2 * (2 * TPROJv) + half * TPROJv + k];
#pragma unroll
            for (int r = 0; r < NR; r++) e[r] += stemb[r][k] * wv;
        }
        float* dst = half ? g_eR : g_eL;
#pragma unroll
        for (int r = 0; r < NR; r++) dst[(row0 + r) * CZv + c2] = e[r];
    }
    __syncthreads();

    float h[NR];
#pragma unroll
    for (int r = 0; r < NR; r++) h[r] = b_n1[c];
    {
        const float4* W1r = (const float4*)(W_n1 + c * CSv);
#pragma unroll 4
        for (int q = 0; q < CSv / 4; q++) {
            float4 wv = W1r[q];
#pragma unroll
            for (int r = 0; r < NR; r++) {
                const float* xr = &sx[r][q * 4];
                h[r] += xr[0] * wv.x + xr[1] * wv.y + xr[2] * wv.z + xr[3] * wv.w;
            }
        }
    }
    __syncthreads();
#pragma unroll
    for (int r = 0; r < NR; r++) sx[r][c] = fmaxf(h[r], 0.0f);
    __syncthreads();

    float o[NR];
#pragma unroll
    for (int r = 0; r < NR; r++) o[r] = b_n2[c];
    {
        const float4* W2r = (const float4*)(W_n2 + c * CSv);
#pragma unroll 4
        for (int q = 0; q < CSv / 4; q++) {
            float4 wv = W2r[q];
#pragma unroll
            for (int r = 0; r < NR; r++) {
                const float* xr = &sx[r][q * 4];
                o[r] += xr[0] * wv.x + xr[1] * wv.y + xr[2] * wv.z + xr[3] * wv.w;
            }
        }
    }
    __syncthreads();
#pragma unroll
    for (int r = 0; r < NR; r++) sx[r][c] = o[r];
    __syncthreads();

    {
        const int w = tid >> 5, l = tid & 31;
        float v[8];
#pragma unroll
        for (int g = 0; g < 8; g++) v[g] = sx[w][g * 32 + l];
        float s = 0.0f;
#pragma unroll
        for (int g = 0; g < 8; g++) s += v[g];
#pragma unroll
        for (int off = 16; off > 0; off >>= 1) s += __shfl_xor_sync(0xffffffffu, s, off);
        float mean = s * (1.0f / 256.0f);
        float sq = 0.0f;
#pragma unroll
        for (int g = 0; g < 8; g++) { float d = v[g] - mean; sq += d * d; }
#pragma unroll
        for (int off = 16; off > 0; off >>= 1) sq += __shfl_xor_sync(0xffffffffu, sq, off);
        float rstd = rsqrtf(sq * (1.0f / 256.0f) + LN_EPS);
        const int row = row0 + w;
#pragma unroll
        for (int g = 0; g < 8; g++) {
            int cc = g * 32 + l;
            out_seq[row * CSv + cc] = (v[g] - mean) * rstd * g_n[cc] + be_n[cc];
        }
    }
}

// ---------------------------------------------------------------------------
// Kernel 3: edge path, fp16x2 GEMMs on tensor cores.
// 128x128 tile; 8 warps in 4(m) x 2(n) grid (32x64 warp tiles) to minimize
// fragment replication.  Coalesced X-build; H writeback via stmatrix.
// ---------------------------------------------------------------------------
#define WSTR 68           // u32 words per row (conflict-free: 68 mod 32 = 4)
#define XH_W 0
#define XL_W (128 * WSTR)
#define WS_W (2 * 128 * WSTR)
#define REL_W (3 * 128 * WSTR)
#define EDGE_SMEM_U32 (REL_W + 128 + 8)
#define EDGE_SMEM_BYTES (EDGE_SMEM_U32 * 4)
#define ESTR 132          // epilogue float stride (128x132 overlays Xh+Xl)

// fp16x2 GEMM pass, warp tile 32(m) x 64(n): acc[2][8][4].
__device__ __forceinline__ void gemm_pass(
    float acc[2][8][4],
    uint32_t aAddrH, uint32_t aAddrL,   // ldsm lane addr (mt=0, kk=0)
    uint32_t bAddr) {                   // ldsm lane addr (p=0, kk=0)
#pragma unroll
    for (int kk = 0; kk < 8; kk++) {
        const uint32_t kb = kk * 32;
        uint32_t ah[2][4], al[2][4], bh[8][2];
#pragma unroll
        for (int p = 0; p < 4; p++)
            ldsm_x4(bh[2 * p][0], bh[2 * p][1], bh[2 * p + 1][0], bh[2 * p + 1][1],
                    bAddr + p * (16 * WSTR * 4) + kb);
#pragma unroll
        for (int mt = 0; mt < 2; mt++) {
            ldsm_x4(ah[mt][0], ah[mt][1], ah[mt][2], ah[mt][3],
                    aAddrH + mt * (16 * WSTR * 4) + kb);
            ldsm_x4(al[mt][0], al[mt][1], al[mt][2], al[mt][3],
                    aAddrL + mt * (16 * WSTR * 4) + kb);
        }
#pragma unroll
        for (int mt = 0; mt < 2; mt++)
#pragma unroll
            for (int nt = 0; nt < 8; nt++) {
                mma16816(acc[mt][nt], al[mt][0], al[mt][1], al[mt][2], al[mt][3],
                         bh[nt][0], bh[nt][1]);
                mma16816(acc[mt][nt], ah[mt][0], ah[mt][1], ah[mt][2], ah[mt][3],
                         bh[nt][0], bh[nt][1]);
            }
    }
}

__global__ __launch_bounds__(256, 2) void edge_kernel(
    const int* __restrict__ seq_idx,
    const float* __restrict__ b_e1, const float* __restrict__ b_e2,
    const float* __restrict__ g_e, const float* __restrict__ be_e,
    float* __restrict__ out_edge) {
    extern __shared__ uint32_t smw[];
    uint32_t* Xh = smw + XH_W;
    uint32_t* Xl = smw + XL_W;
    uint32_t* Ws = smw + WS_W;
    int* s_rel = (int*)(smw + REL_W);
    float* E = (float*)smw;  // epilogue overlay: 128x132 floats < Xh+Xl region

    const int tid = threadIdx.x, w = tid >> 5, l = tid & 31;
    const int g = l >> 2, tig = l & 3;
    const int wm = w >> 1, wn = w & 1;     // 4 x 2 warp grid, 32x64 tiles
    const int m0 = wm * 32, n0 = wn * 64;
    const int bid = blockIdx.x;
    const int jt = bid % 3, i = (bid / 3) % NN, b = bid / (3 * NN);
    const int j0 = jt * 128;

    // ldmatrix / stmatrix lane addresses (byte, shared space).
    const uint32_t sb = smem_u32(smw);
    const int l16 = l & 15, lhi = l >> 4;
    // A (and H-stmatrix) addressing: row m0 + l16, k-offset lhi*16B
    const uint32_t aAddrH = sb + ((m0 + l16) * WSTR + lhi * 4) * 4;
    const uint32_t aAddrL = aAddrH + XL_W * 4;
    // B addressing (two 8n x 16k tiles per ldsm): n row n0 + (l&7) + (l>>4)*8
    const int nB = n0 + (l & 7) + (lhi << 3);
    const int kofB = ((l >> 3) & 1) << 2;
    const uint32_t bAddr = sb + (WS_W + nB * WSTR + kofB) * 4;

    if (tid < 128) {
        int rel = seq_idx[b * NN + i] - seq_idx[b * NN + j0 + tid] + 1000;
        s_rel[tid] = min(max(rel, 0), 2047);
    }
    // stage W1 (fp16, padded rows): 2048 float4
    {
        const float4* Wsrc = (const float4*)g_W1f;
        for (int m = tid; m < 2048; m += 256) {
            int n = m >> 4, c4 = m & 15;
            *(float4*)&Ws[n * WSTR + c4 * 4] = Wsrc[m];
        }
    }
    __syncthreads();

    // Build X = relu(table[rel_j] + L_i + R_j), fp16 hi/lo, warp-per-row.
    {
        const float4 Lv = ((const float4*)(g_eL + (size_t)(b * NN + i) * CZv))[l];
        unsigned long long* Xh64 = (unsigned long long*)Xh;
        unsigned long long* Xl64 = (unsigned long long*)Xl;
#pragma unroll 4
        for (int it = 0; it < 16; it++) {
            const int r = w * 16 + it;
            float4 tv = ((const float4*)(g_table + (size_t)s_rel[r] * CZv))[l];
            float4 rv = ((const float4*)(g_eR + (size_t)(b * NN + j0 + r) * CZv))[l];
            float x0 = fmaxf(tv.x + Lv.x + rv.x, 0.0f);
            float x1 = fmaxf(tv.y + Lv.y + rv.y, 0.0f);
            float x2 = fmaxf(tv.z + Lv.z + rv.z, 0.0f);
            float x3 = fmaxf(tv.w + Lv.w + rv.w, 0.0f);
            float r0, r1, r2, r3;
            uint32_t h01 = packh_hi2(x0, x1, r0, r1);
            uint32_t h23 = packh_hi2(x2, x3, r2, r3);
            int idx64 = r * 34 + l;   // lane l covers u64 slot l (contiguous 256B)
            Xh64[idx64] = ((unsigned long long)h23 << 32) | h01;
            Xl64[idx64] = ((unsigned long long)packh2(r2, r3) << 32) | packh2(r0, r1);
        }
    }
    __syncthreads();

    // ---- GEMM1: acc = X @ W1^T (fp16x2) ----
    float acc[2][8][4];
#pragma unroll
    for (int mt = 0; mt < 2; mt++)
#pragma unroll
        for (int nt = 0; nt < 8; nt++)
#pragma unroll
            for (int e = 0; e < 4; e++) acc[mt][nt][e] = 0.0f;
    gemm_pass(acc, aAddrH, aAddrL, bAddr);
    __syncthreads();  // all GEMM1 reads of X/W done

    // H = relu(acc + b_e1) -> X buffers via stmatrix (hi and lo); stage W2.
#pragma unroll
    for (int mt = 0; mt < 2; mt++) {
#pragma unroll
        for (int ntq = 0; ntq < 4; ntq++) {
            const int nt0 = 2 * ntq, nt1 = nt0 + 1;
            const int c0 = n0 + nt0 * 8 + 2 * tig;
            const int c1 = n0 + nt1 * 8 + 2 * tig;
            float bb0 = __ldg(b_e1 + c0), bb1 = __ldg(b_e1 + c0 + 1);
            float bb2 = __ldg(b_e1 + c1), bb3 = __ldg(b_e1 + c1 + 1);
            float q0, q1, q2, q3, q4, q5, q6, q7;
            uint32_t m0h = packh_hi2(fmaxf(acc[mt][nt0][0] + bb0, 0.0f),
                                     fmaxf(acc[mt][nt0][1] + bb1, 0.0f), q0, q1);
            uint32_t m1h = packh_hi2(fmaxf(acc[mt][nt0][2] + bb0, 0.0f),
                                     fmaxf(acc[mt][nt0][3] + bb1, 0.0f), q2, q3);
            uint32_t m2h = packh_hi2(fmaxf(acc[mt][nt1][0] + bb2, 0.0f),
                                     fmaxf(acc[mt][nt1][1] + bb3, 0.0f), q4, q5);
            uint32_t m3h = packh_hi2(fmaxf(acc[mt][nt1][2] + bb2, 0.0f),
                                     fmaxf(acc[mt][nt1][3] + bb3, 0.0f), q6, q7);
            // store address: row m0+mt*16+l16, col words n0/2 + ntq*8 + lhi*4
            uint32_t sa = sb + ((m0 + mt * 16 + l16) * WSTR
                                + (n0 >> 1) + ntq * 8 + lhi * 4) * 4;
            stsm_x4(sa, m0h, m1h, m2h, m3h);
            stsm_x4(sa + XL_W * 4, packh2(q0, q1), packh2(q2, q3),
                    packh2(q4, q5), packh2(q6, q7));
        }
    }
    {
        const float4* Wsrc = (const float4*)g_W2f;
        for (int m = tid; m < 2048; m += 256) {
            int n = m >> 4, c4 = m & 15;
            *(float4*)&Ws[n * WSTR + c4 * 4] = Wsrc[m];
        }
    }
    __syncthreads();

    // ---- GEMM2: acc = H @ W2^T (fp16x2) ----
#pragma unroll
    for (int mt = 0; mt < 2; mt++)
#pragma unroll
        for (int nt = 0; nt < 8; nt++)
#pragma unroll
            for (int e = 0; e < 4; e++) acc[mt][nt][e] = 0.0f;
    gemm_pass(acc, aAddrH, aAddrL, bAddr);
    __syncthreads();  // GEMM2 reads done; E overlay now safe

    // O = acc + b_e2 -> E[r][c] (float2 stores, pad 132)
#pragma unroll
    for (int mt = 0; mt < 2; mt++) {
        int r0w = m0 + mt * 16 + g;
#pragma unroll
        for (int nt = 0; nt < 8; nt++) {
            int c0 = n0 + nt * 8 + 2 * tig;
            float bb0 = __ldg(b_e2 + c0), bb1 = __ldg(b_e2 + c0 + 1);
            *(float2*)&E[r0w * ESTR + c0] =
                make_float2(acc[mt][nt][0] + bb0, acc[mt][nt][1] + bb1);
            *(float2*)&E[(r0w + 8) * ESTR + c0] =
                make_float2(acc[mt][nt][2] + bb0, acc[mt][nt][3] + bb1);
        }
    }
    __syncthreads();

    // LayerNorm + coalesced store: warp w handles rows w*16..w*16+15.
    {
        const float ge0 = g_e[l], ge1 = g_e[32 + l], ge2 = g_e[64 + l], ge3 = g_e[96 + l];
        const float be0 = be_e[l], be1 = be_e[32 + l], be2 = be_e[64 + l], be3 = be_e[96 + l];
#pragma unroll 2
        for (int rr = 0; rr < 16; rr++) {
            const int r = w * 16 + rr;
            float v0 = E[r * ESTR + l];
            float v1 = E[r * ESTR + 32 + l];
            float v2 = E[r * ESTR + 64 + l];
            float v3 = E[r * ESTR + 96 + l];
            float s = v0 + v1 + v2 + v3;
#pragma unroll
            for (int off = 16; off > 0; off >>= 1) s += __shfl_xor_sync(0xffffffffu, s, off);
            float mean = s * (1.0f / 128.0f);
            float d0 = v0 - mean, d1 = v1 - mean, d2 = v2 - mean, d3 = v3 - mean;
            float sq = d0 * d0 + d1 * d1 + d2 * d2 + d3 * d3;
#pragma unroll
            for (int off = 16; off > 0; off >>= 1) sq += __shfl_xor_sync(0xffffffffu, sq, off);
            float rstd = rsqrtf(sq * (1.0f / 128.0f) + LN_EPS);
            float* dst = out_edge + ((size_t)(b * NN + i) * NN + (j0 + r)) * CZv;
            dst[l] = d0 * rstd * ge0 + be0;
            dst[32 + l] = d1 * rstd * ge1 + be1;
            dst[64 + l] = d2 * rstd * ge2 + be2;
            dst[96 + l] = d3 * rstd * ge3 + be3;
        }
    }
}

// ===========================================================================
extern "C" void kernel_launch(void* const* d_in, const int* in_sizes, int n_in,
                              void* d_out, int out_size) {
    const int* seq_idx = (const int*)d_in[0];
    const float* seq_feat = (const float*)d_in[1];
    const float* timestep = (const float*)d_in[2];
    const float* frame_mask = (const float*)d_in[3];
    const float* W_npos = (const float*)d_in[4];
    const float* b_npos = (const float*)d_in[5];
    const float* W_ntf = (const float*)d_in[6];
    const float* b_ntf = (const float*)d_in[7];
    const float* W_ntime = (const float*)d_in[8];
    const float* b_ntime = (const float*)d_in[9];
    const float* W_n1 = (const float*)d_in[10];
    const float* b_n1 = (const float*)d_in[11];
    const float* W_n2 = (const float*)d_in[12];
    const float* b_n2 = (const float*)d_in[13];
    const float* g_n = (const float*)d_in[14];
    const float* be_n = (const float*)d_in[15];
    const float* W_epos = (const float*)d_in[16];
    const float* b_epos = (const float*)d_in[17];
    const float* W_etf = (const float*)d_in[18];
    const float* b_etf = (const float*)d_in[19];
    const float* W_etime = (const float*)d_in[20];
    const float* b_etime = (const float*)d_in[21];
    const float* W_e1 = (const float*)d_in[22];
    const float* b_e1 = (const float*)d_in[23];
    const float* W_e2 = (const float*)d_in[24];
    const float* b_e2 = (const float*)d_in[25];
    const float* g_e = (const float*)d_in[26];
    const float* be_e = (const float*)d_in[27];

    float* out = (float*)d_out;
    float* out_seq = out;                   // [B,N,CS] first
    float* out_edge = out + NB * NN * CSv;  // then [B,N,N,CZ]

    static int configured = 0;
    if (!configured) {
        cudaFuncSetAttribute(edge_kernel, cudaFuncAttributeMaxDynamicSharedMemorySize,
                             EDGE_SMEM_BYTES);
        configured = 1;
    }

    prep_w<<<64, 256>>>(W_e1, W_e2);
    table_kernel<<<2048, 128>>>(W_epos, b_epos, b_etf, b_etime);
    node_kernel<<<NB * NN / NR, 256>>>(seq_idx, seq_feat, timestep, frame_mask,
                                       W_npos, b_npos, W_ntf, b_ntf, W_ntime, b_ntime,
                                       W_n1, b_n1, W_n2, b_n2, g_n, be_n,
                                       W_etf, W_etime, out_seq);
    edge_kernel<<<NB * NN * 3, 256, EDGE_SMEM_BYTES>>>(seq_idx, b_e1, b_e2,
                                                       g_e, be_e, out_edge);
}

// round 10
// speedup vs baseline: 2.2308x; 1.0047x over previous
#include <cuda_runtime.h>
#include <cuda_fp16.h>
#include <cstdint>

#define NB 2
#define NN 384
#define TFv 22
#define POSv 32
#define TPROJv 33
#define CSv 256
#define CZv 128
#define LN_EPS 1e-5f
#define PI_F 3.14159265358979323846f

// rel in [-999, 999] -> index rel+1000; table sized 2048 for safety.
__device__ float g_table[2048 * CZv];
__device__ float g_eL[NB * NN * CZv];
__device__ float g_eR[NB * NN * CZv];
// Edge weights rounded to fp16, [c][k] row-major, 128x128 each.
__device__ __half g_W1f[CZv * CZv], g_W2f[CZv * CZv];

// ---------------------------------------------------------------------------
// helpers
// ---------------------------------------------------------------------------
__device__ __forceinline__ uint32_t smem_u32(const void* p) {
    uint32_t a;
    asm("{ .reg .u64 t; cvta.to.shared.u64 t, %1; cvt.u32.u64 %0, t; }"
        : "=r"(a) : "l"(p));
    return a;
}
__device__ __forceinline__ uint32_t packh_hi2(float x0, float x1, float& r0, float& r1) {
    __half2 v = __floats2half2_rn(x0, x1);
    r0 = x0 - __half2float(__low2half(v));
    r1 = x1 - __half2float(__high2half(v));
    return *reinterpret_cast<uint32_t*>(&v);
}
__device__ __forceinline__ uint32_t packh2(float r0, float r1) {
    __half2 v = __floats2half2_rn(r0, r1);
    return *reinterpret_cast<uint32_t*>(&v);
}
__device__ __forceinline__ void mma16816(float* c, uint32_t a0, uint32_t a1,
                                         uint32_t a2, uint32_t a3,
                                         uint32_t b0, uint32_t b1) {
    asm volatile(
        "mma.sync.aligned.m16n8k16.row.col.f32.f16.f16.f32 "
        "{%0,%1,%2,%3}, {%4,%5,%6,%7}, {%8,%9}, {%0,%1,%2,%3};"
        : "+f"(c[0]), "+f"(c[1]), "+f"(c[2]), "+f"(c[3])
        : "r"(a0), "r"(a1), "r"(a2), "r"(a3), "r"(b0), "r"(b1));
}
__device__ __forceinline__ void ldsm_x4(uint32_t& r0, uint32_t& r1,
                                        uint32_t& r2, uint32_t& r3, uint32_t addr) {
    asm volatile("ldmatrix.sync.aligned.m8n8.x4.shared.b16 {%0,%1,%2,%3}, [%4];"
                 : "=r"(r0), "=r"(r1), "=r"(r2), "=r"(r3) : "r"(addr));
}
__device__ __forceinline__ void stsm_x4(uint32_t addr, uint32_t r0, uint32_t r1,
                                        uint32_t r2, uint32_t r3) {
    asm volatile("stmatrix.sync.aligned.m8n8.x4.shared.b16 [%0], {%1,%2,%3,%4};"
                 :: "r"(addr), "r"(r0), "r"(r1), "r"(r2), "r"(r3) : "memory");
}

// ---------------------------------------------------------------------------
// Fused setup kernel: blocks [0,1024) table (2 rel/block),
// [1024,1120) node path, [1120,1184) prep_w.  256 threads everywhere.
// ---------------------------------------------------------------------------
#define NR 8
#define TBLK 1024
#define NODEB (NB * NN / NR)   // 96

__global__ __launch_bounds__(256) void setup_kernel(
    const int* __restrict__ seq_idx, const float* __restrict__ seq_feat,
    const float* __restrict__ timestep, const float* __restrict__ frame_mask,
    const float* __restrict__ W_npos, const float* __restrict__ b_npos,
    const float* __restrict__ W_ntf, const float* __restrict__ b_ntf,
    const float* __restrict__ W_ntime, const float* __restrict__ b_ntime,
    const float* __restrict__ W_n1, const float* __restrict__ b_n1,
    const float* __restrict__ W_n2, const float* __restrict__ b_n2,
    const float* __restrict__ g_n, const float* __restrict__ be_n,
    const float* __restrict__ W_epos, const float* __restrict__ b_epos,
    const float* __restrict__ b_etf, const float* __restrict__ b_etime,
    const float* __restrict__ W_etf, const float* __restrict__ W_etime,
    const float* __restrict__ W_e1, const float* __restrict__ W_e2,
    float* __restrict__ out_seq) {
    __shared__ float su[4352];   // union: table 4288 floats / node 2784 floats
    const int tid = threadIdx.x;
    const int bid = blockIdx.x;

    if (bid < TBLK) {
        // ---- table: rel rows bid*2 and bid*2+1 ----
        float* sWe = su;              // 128*33
        float* emb = su + 4224;       // 2*32
        const int half = tid >> 7, c = tid & 127;
        for (int m = tid; m < CZv * POSv; m += 256)
            sWe[(m >> 5) * 33 + (m & 31)] = W_epos[m];
        const int relv = bid * 2 + half - 1000;
        if (c < 16) {
            float p = powf(2056.0f, (float)c * (1.0f / 16.0f));
            float ang = ((float)relv * PI_F) / p;
            emb[half * 32 + c] = sinf(ang);
            emb[half * 32 + c + 16] = cosf(ang);
        }
        __syncthreads();
        float acc = b_epos[c] + b_etf[c] + b_etime[c];
#pragma unroll
        for (int k = 0; k < POSv; k++) acc += emb[half * 32 + k] * sWe[c * 33 + k];
        g_table[(bid * 2 + half) * CZv + c] = acc;
        return;
    }
    if (bid >= TBLK + NODEB) {
        // ---- prep_w ----
        int t = (bid - TBLK - NODEB) * 256 + tid;
        g_W1f[t] = __float2half_rn(W_e1[t]);
        g_W2f[t] = __float2half_rn(W_e2[t]);
        return;
    }

    // ---- node path: 8 rows ----
    float (*spemb)[POSv] = (float(*)[POSv])su;            // 8*32 = 256
    float (*stemb)[36] = (float(*)[36])(su + 256);        // 8*36 = 288
    float (*sfeat)[24] = (float(*)[24])(su + 544);        // 8*24 = 192
    float (*sx)[CSv] = (float(*)[CSv])(su + 736);         // 8*256 = 2048
    const int row0 = (bid - TBLK) * NR;

    {
        const int r = tid >> 5, j = tid & 31;
        const int row = row0 + r;
        const int b = row / NN;
        if (j < TFv) sfeat[r][j] = seq_feat[row * TFv + j];
        if (j < 16) {
            float p = powf(2056.0f, (float)j * (1.0f / 16.0f));
            float ang = ((float)seq_idx[row] * PI_F) / p;
            spemb[r][j] = sinf(ang);
            spemb[r][j + 16] = cosf(ang);
            float fm = frame_mask[row];
            float tt = timestep[b] * fm;
            float fr = expf(-0.6140226914650789f * (float)j);
            float a2 = tt * fr;
            stemb[r][j] = sinf(a2);
            stemb[r][j + 16] = cosf(a2);
            if (j == 0) stemb[r][32] = fm;
        }
    }
    __syncthreads();

    const int c = tid;
    float acc[NR];
    {
        float base = b_npos[c] + b_ntf[c] + b_ntime[c];
#pragma unroll
        for (int r = 0; r < NR; r++) acc[r] = base;
    }
#pragma unroll
    for (int k = 0; k < POSv; k++) {
        float wv = W_npos[c * POSv + k];
#pragma unroll
        for (int r = 0; r < NR; r++) acc[r] += spemb[r][k] * wv;
    }
#pragma unroll
    for (int k = 0; k < TFv; k++) {
        float wv = W_ntf[c * TFv + k];
#pragma unroll
        for (int r = 0; r < NR; r++) acc[r] += sfeat[r][k] * wv;
    }
#pragma unroll
    for (int k = 0; k < TPROJv; k++) {
        float wv = W_ntime[c * TPROJv + k];
#pragma unroll
        for (int r = 0; r < NR; r++) acc[r] += stemb[r][k] * wv;
    }
#pragma unroll
    for (int r = 0; r < NR; r++) sx[r][c] = fmaxf(acc[r], 0.0f);

    {
        const int c2 = tid & 127, half = tid >> 7;
        float e[NR];
#pragma unroll
        for (int r = 0; r < NR; r++) e[r] = 0.0f;
#pragma unroll
        for (int k = 0; k < TFv; k++) {
            float wv = W_etf[c2 * (2 * TFv) + half * TFv + k];
#pragma unroll
            for (int r = 0; r < NR; r++) e[r] += sfeat[r][k] * wv;
        }
#pragma unroll
        for (int k = 0; k < TPROJv; k++) {
            float wv = W_etime[c2 * (2 * TPROJv) + half * TPROJv + k];
#pragma unroll
            for (int r = 0; r < NR; r++) e[r] += stemb[r][k] * wv;
        }
        float* dst = half ? g_eR : g_eL;
#pragma unroll
        for (int r = 0; r < NR; r++) dst[(row0 + r) * CZv + c2] = e[r];
    }
    __syncthreads();

    float h[NR];
#pragma unroll
    for (int r = 0; r < NR; r++) h[r] = b_n1[c];
    {
        const float4* W1r = (const float4*)(W_n1 + c * CSv);
#pragma unroll 4
        for (int q = 0; q < CSv / 4; q++) {
            float4 wv = W1r[q];
#pragma unroll
            for (int r = 0; r < NR; r++) {
                float4 xv = *(const float4*)&sx[r][q * 4];
                h[r] += xv.x * wv.x + xv.y * wv.y + xv.z * wv.z + xv.w * wv.w;
            }
        }
    }
    __syncthreads();
#pragma unroll
    for (int r = 0; r < NR; r++) sx[r][c] = fmaxf(h[r], 0.0f);
    __syncthreads();

    float o[NR];
#pragma unroll
    for (int r = 0; r < NR; r++) o[r] = b_n2[c];
    {
        const float4* W2r = (const float4*)(W_n2 + c * CSv);
#pragma unroll 4
        for (int q = 0; q < CSv / 4; q++) {
            float4 wv = W2r[q];
#pragma unroll
            for (int r = 0; r < NR; r++) {
                float4 xv = *(const float4*)&sx[r][q * 4];
                o[r] += xv.x * wv.x + xv.y * wv.y + xv.z * wv.z + xv.w * wv.w;
            }
        }
    }
    __syncthreads();
#pragma unroll
    for (int r = 0; r < NR; r++) sx[r][c] = o[r];
    __syncthreads();

    {
        const int w = tid >> 5, l = tid & 31;
        float v[8];
#pragma unroll
        for (int g = 0; g < 8; g++) v[g] = sx[w][g * 32 + l];
        float s = 0.0f;
#pragma unroll
        for (int g = 0; g < 8; g++) s += v[g];
#pragma unroll
        for (int off = 16; off > 0; off >>= 1) s += __shfl_xor_sync(0xffffffffu, s, off);
        float mean = s * (1.0f / 256.0f);
        float sq = 0.0f;
#pragma unroll
        for (int g = 0; g < 8; g++) { float d = v[g] - mean; sq += d * d; }
#pragma unroll
        for (int off = 16; off > 0; off >>= 1) sq += __shfl_xor_sync(0xffffffffu, sq, off);
        float rstd = rsqrtf(sq * (1.0f / 256.0f) + LN_EPS);
        const int row = row0 + w;
#pragma unroll
        for (int g = 0; g < 8; g++) {
            int cc = g * 32 + l;
            out_seq[row * CSv + cc] = (v[g] - mean) * rstd * g_n[cc] + be_n[cc];
        }
    }
}

// ---------------------------------------------------------------------------
// Edge kernel: fp16x2 GEMMs on tensor cores (as R9), nt split into halves
// to lower register pressure and improve cross-kk pipelining.
// ---------------------------------------------------------------------------
#define WSTR 68
#define XH_W 0
#define XL_W (128 * WSTR)
#define WS_W (2 * 128 * WSTR)
#define REL_W (3 * 128 * WSTR)
#define EDGE_SMEM_U32 (REL_W + 128 + 8)
#define EDGE_SMEM_BYTES (EDGE_SMEM_U32 * 4)
#define ESTR 132

// fp16x2 GEMM pass, warp tile 32(m) x 64(n): acc[2][8][4].
__device__ __forceinline__ void gemm_pass(
    float acc[2][8][4],
    uint32_t aAddrH, uint32_t aAddrL,
    uint32_t bAddr) {
#pragma unroll
    for (int kk = 0; kk < 8; kk++) {
        const uint32_t kb = kk * 32;
        uint32_t ah[2][4], al[2][4];
#pragma unroll
        for (int mt = 0; mt < 2; mt++) {
            ldsm_x4(ah[mt][0], ah[mt][1], ah[mt][2], ah[mt][3],
                    aAddrH + mt * (16 * WSTR * 4) + kb);
            ldsm_x4(al[mt][0], al[mt][1], al[mt][2], al[mt][3],
                    aAddrL + mt * (16 * WSTR * 4) + kb);
        }
#pragma unroll
        for (int h = 0; h < 2; h++) {   // two n-halves of 32 cols each
            uint32_t bh[4][2];
#pragma unroll
            for (int p = 0; p < 2; p++)
                ldsm_x4(bh[2 * p][0], bh[2 * p][1], bh[2 * p + 1][0], bh[2 * p + 1][1],
                        bAddr + (h * 2 + p) * (16 * WSTR * 4) + kb);
#pragma unroll
            for (int mt = 0; mt < 2; mt++)
#pragma unroll
                for (int nt = 0; nt < 4; nt++) {
                    float* a = acc[mt][h * 4 + nt];
                    mma16816(a, al[mt][0], al[mt][1], al[mt][2], al[mt][3],
                             bh[nt][0], bh[nt][1]);
                    mma16816(a, ah[mt][0], ah[mt][1], ah[mt][2], ah[mt][3],
                             bh[nt][0], bh[nt][1]);
                }
        }
    }
}

__global__ __launch_bounds__(256, 2) void edge_kernel(
    const int* __restrict__ seq_idx,
    const float* __restrict__ b_e1, const float* __restrict__ b_e2,
    const float* __restrict__ g_e, const float* __restrict__ be_e,
    float* __restrict__ out_edge) {
    extern __shared__ uint32_t smw[];
    uint32_t* Xh = smw + XH_W;
    uint32_t* Xl = smw + XL_W;
    uint32_t* Ws = smw + WS_W;
    int* s_rel = (int*)(smw + REL_W);
    float* E = (float*)smw;

    const int tid = threadIdx.x, w = tid >> 5, l = tid & 31;
    const int g = l >> 2, tig = l & 3;
    const int wm = w >> 1, wn = w & 1;     // 4 x 2 warp grid, 32x64 tiles
    const int m0 = wm * 32, n0 = wn * 64;
    const int bid = blockIdx.x;
    const int jt = bid % 3, i = (bid / 3) % NN, b = bid / (3 * NN);
    const int j0 = jt * 128;

    const uint32_t sb = smem_u32(smw);
    const int l16 = l & 15, lhi = l >> 4;
    const uint32_t aAddrH = sb + ((m0 + l16) * WSTR + lhi * 4) * 4;
    const uint32_t aAddrL = aAddrH + XL_W * 4;
    const int nB = n0 + (l & 7) + (lhi << 3);
    const int kofB = ((l >> 3) & 1) << 2;
    const uint32_t bAddr = sb + (WS_W + nB * WSTR + kofB) * 4;

    if (tid < 128) {
        int rel = seq_idx[b * NN + i] - seq_idx[b * NN + j0 + tid] + 1000;
        s_rel[tid] = min(max(rel, 0), 2047);
    }
    {
        const float4* Wsrc = (const float4*)g_W1f;
        for (int m = tid; m < 2048; m += 256) {
            int n = m >> 4, c4 = m & 15;
            *(float4*)&Ws[n * WSTR + c4 * 4] = Wsrc[m];
        }
    }
    __syncthreads();

    // Build X = relu(table[rel_j] + L_i + R_j), fp16 hi/lo, warp-per-row.
    {
        const float4 Lv = ((const float4*)(g_eL + (size_t)(b * NN + i) * CZv))[l];
        unsigned long long* Xh64 = (unsigned long long*)Xh;
        unsigned long long* Xl64 = (unsigned long long*)Xl;
#pragma unroll 4
        for (int it = 0; it < 16; it++) {
            const int r = w * 16 + it;
            float4 tv = ((const float4*)(g_table + (size_t)s_rel[r] * CZv))[l];
            float4 rv = ((const float4*)(g_eR + (size_t)(b * NN + j0 + r) * CZv))[l];
            float x0 = fmaxf(tv.x + Lv.x + rv.x, 0.0f);
            float x1 = fmaxf(tv.y + Lv.y + rv.y, 0.0f);
            float x2 = fmaxf(tv.z + Lv.z + rv.z, 0.0f);
            float x3 = fmaxf(tv.w + Lv.w + rv.w, 0.0f);
            float r0, r1, r2, r3;
            uint32_t h01 = packh_hi2(x0, x1, r0, r1);
            uint32_t h23 = packh_hi2(x2, x3, r2, r3);
            int idx64 = r * 34 + l;
            Xh64[idx64] = ((unsigned long long)h23 << 32) | h01;
            Xl64[idx64] = ((unsigned long long)packh2(r2, r3) << 32) | packh2(r0, r1);
        }
    }
    __syncthreads();

    // ---- GEMM1 ----
    float acc[2][8][4];
#pragma unroll
    for (int mt = 0; mt < 2; mt++)
#pragma unroll
        for (int nt = 0; nt < 8; nt++)
#pragma unroll
            for (int e = 0; e < 4; e++) acc[mt][nt][e] = 0.0f;
    gemm_pass(acc, aAddrH, aAddrL, bAddr);
    __syncthreads();

    // H = relu(acc + b_e1) -> X buffers via stmatrix; stage W2.
#pragma unroll
    for (int mt = 0; mt < 2; mt++) {
#pragma unroll
        for (int ntq = 0; ntq < 4; ntq++) {
            const int nt0 = 2 * ntq, nt1 = nt0 + 1;
            const int c0 = n0 + nt0 * 8 + 2 * tig;
            const int c1 = n0 + nt1 * 8 + 2 * tig;
            float bb0 = __ldg(b_e1 + c0), bb1 = __ldg(b_e1 + c0 + 1);
            float bb2 = __ldg(b_e1 + c1), bb3 = __ldg(b_e1 + c1 + 1);
            float q0, q1, q2, q3, q4, q5, q6, q7;
            uint32_t m0h = packh_hi2(fmaxf(acc[mt][nt0][0] + bb0, 0.0f),
                                     fmaxf(acc[mt][nt0][1] + bb1, 0.0f), q0, q1);
            uint32_t m1h = packh_hi2(fmaxf(acc[mt][nt0][2] + bb0, 0.0f),
                                     fmaxf(acc[mt][nt0][3] + bb1, 0.0f), q2, q3);
            uint32_t m2h = packh_hi2(fmaxf(acc[mt][nt1][0] + bb2, 0.0f),
                                     fmaxf(acc[mt][nt1][1] + bb3, 0.0f), q4, q5);
            uint32_t m3h = packh_hi2(fmaxf(acc[mt][nt1][2] + bb2, 0.0f),
                                     fmaxf(acc[mt][nt1][3] + bb3, 0.0f), q6, q7);
            uint32_t sa = sb + ((m0 + mt * 16 + l16) * WSTR
                                + (n0 >> 1) + ntq * 8 + lhi * 4) * 4;
            stsm_x4(sa, m0h, m1h, m2h, m3h);
            stsm_x4(sa + XL_W * 4, packh2(q0, q1), packh2(q2, q3),
                    packh2(q4, q5), packh2(q6, q7));
        }
    }
    {
        const float4* Wsrc = (const float4*)g_W2f;
        for (int m = tid; m < 2048; m += 256) {
            int n = m >> 4, c4 = m & 15;
            *(float4*)&Ws[n * WSTR + c4 * 4] = Wsrc[m];
        }
    }
    __syncthreads();

    // ---- GEMM2 ----
#pragma unroll
    for (int mt = 0; mt < 2; mt++)
#pragma unroll
        for (int nt = 0; nt < 8; nt++)
#pragma unroll
            for (int e = 0; e < 4; e++) acc[mt][nt][e] = 0.0f;
    gemm_pass(acc, aAddrH, aAddrL, bAddr);
    __syncthreads();

    // O = acc + b_e2 -> E[r][c]
#pragma unroll
    for (int mt = 0; mt < 2; mt++) {
        int r0w = m0 + mt * 16 + g;
#pragma unroll
        for (int nt = 0; nt < 8; nt++) {
            int c0 = n0 + nt * 8 + 2 * tig;
            float bb0 = __ldg(b_e2 + c0), bb1 = __ldg(b_e2 + c0 + 1);
            *(float2*)&E[r0w * ESTR + c0] =
                make_float2(acc[mt][nt][0] + bb0, acc[mt][nt][1] + bb1);
            *(float2*)&E[(r0w + 8) * ESTR + c0] =
                make_float2(acc[mt][nt][2] + bb0, acc[mt][nt][3] + bb1);
        }
    }
    __syncthreads();

    // LayerNorm + coalesced store.
    {
        const float ge0 = g_e[l], ge1 = g_e[32 + l], ge2 = g_e[64 + l], ge3 = g_e[96 + l];
        const float be0 = be_e[l], be1 = be_e[32 + l], be2 = be_e[64 + l], be3 = be_e[96 + l];
#pragma unroll 2
        for (int rr = 0; rr < 16; rr++) {
            const int r = w * 16 + rr;
            float v0 = E[r * ESTR + l];
            float v1 = E[r * ESTR + 32 + l];
            float v2 = E[r * ESTR + 64 + l];
            float v3 = E[r * ESTR + 96 + l];
            float s = v0 + v1 + v2 + v3;
#pragma unroll
            for (int off = 16; off > 0; off >>= 1) s += __shfl_xor_sync(0xffffffffu, s, off);
            float mean = s * (1.0f / 128.0f);
            float d0 = v0 - mean, d1 = v1 - mean, d2 = v2 - mean, d3 = v3 - mean;
            float sq = d0 * d0 + d1 * d1 + d2 * d2 + d3 * d3;
#pragma unroll
            for (int off = 16; off > 0; off >>= 1) sq += __shfl_xor_sync(0xffffffffu, sq, off);
            float rstd = rsqrtf(sq * (1.0f / 128.0f) + LN_EPS);
            float* dst = out_edge + ((size_t)(b * NN + i) * NN + (j0 + r)) * CZv;
            dst[l] = d0 * rstd * ge0 + be0;
            dst[32 + l] = d1 * rstd * ge1 + be1;
            dst[64 + l] = d2 * rstd * ge2 + be2;
            dst[96 + l] = d3 * rstd * ge3 + be3;
        }
    }
}

// ===========================================================================
extern "C" void kernel_launch(void* const* d_in, const int* in_sizes, int n_in,
                              void* d_out, int out_size) {
    const int* seq_idx = (const int*)d_in[0];
    const float* seq_feat = (const float*)d_in[1];
    const float* timestep = (const float*)d_in[2];
    const float* frame_mask = (const float*)d_in[3];
    const float* W_npos = (const float*)d_in[4];
    const float* b_npos = (const float*)d_in[5];
    const float* W_ntf = (const float*)d_in[6];
    const float* b_ntf = (const float*)d_in[7];
    const float* W_ntime = (const float*)d_in[8];
    const float* b_ntime = (const float*)d_in[9];
    const float* W_n1 = (const float*)d_in[10];
    const float* b_n1 = (const float*)d_in[11];
    const float* W_n2 = (const float*)d_in[12];
    const float* b_n2 = (const float*)d_in[13];
    const float* g_n = (const float*)d_in[14];
    const float* be_n = (const float*)d_in[15];
    const float* W_epos = (const float*)d_in[16];
    const float* b_epos = (const float*)d_in[17];
    const float* W_etf = (const float*)d_in[18];
    const float* b_etf = (const float*)d_in[19];
    const float* W_etime = (const float*)d_in[20];
    const float* b_etime = (const float*)d_in[21];
    const float* W_e1 = (const float*)d_in[22];
    const float* b_e1 = (const float*)d_in[23];
    const float* W_e2 = (const float*)d_in[24];
    const float* b_e2 = (const float*)d_in[25];
    const float* g_e = (const float*)d_in[26];
    const float* be_e = (const float*)d_in[27];

    float* out = (float*)d_out;
    float* out_seq = out;                   // [B,N,CS] first
    float* out_edge = out + NB * NN * CSv;  // then [B,N,N,CZ]

    static int configured = 0;
    if (!configured) {
        cudaFuncSetAttribute(edge_kernel, cudaFuncAttributeMaxDynamicSharedMemorySize,
                             EDGE_SMEM_BYTES);
        configured = 1;
    }

    setup_kernel<<<TBLK + NODEB + 64, 256>>>(
        seq_idx, seq_feat, timestep, frame_mask,
        W_npos, b_npos, W_ntf, b_ntf, W_ntime, b_ntime,
        W_n1, b_n1, W_n2, b_n2, g_n, be_n,
        W_epos, b_epos, b_etf, b_etime, W_etf, W_etime,
        W_e1, W_e2, out_seq);
    edge_kernel<<<NB * NN * 3, 256, EDGE_SMEM_BYTES>>>(seq_idx, b_e1, b_e2,
                                                       g_e, be_e, out_edge);
}